// round 7
// baseline (speedup 1.0000x reference)
#include <cuda_runtime.h>
#include <cstdint>

// Problem constants (fixed by the dataset)
#define NMAX   500000
#define EMAX   2000000
#define EMB    32
#define IN_DIM 65
#define TB     256

// Scratch (allocation-free rule: __device__ globals)
__device__ int g_total;
__device__ __align__(128) int  g_cnt[NMAX];     // indegree (excl. self-loop)
__device__ __align__(128) int  g_base[NMAX];    // CSR segment start
__device__ __align__(128) int  g_rank[EMAX];    // edge rank within its dst segment
__device__ __align__(128) int2 g_packed[NMAX];  // {dinv bits, x}
__device__ __align__(128) int2 g_elist[EMAX];   // CSR edge payload: {dinv_src bits, x_src}

// ---------------------------------------------------------------------------
// K1: zero counts, out[g] = b_out[0], reset bump allocator
// ---------------------------------------------------------------------------
__global__ void k_init(float* __restrict__ out, const float* __restrict__ b_out,
                       int N, int G) {
    int i = blockIdx.x * blockDim.x + threadIdx.x;
    if (i < N) g_cnt[i] = 0;
    if (i < G) out[i] = b_out[0];
    if (i == 0) g_total = 0;
}

// ---------------------------------------------------------------------------
// K2: indegree count; returned old value = this edge's rank in its segment.
//     4 edges/thread via int4 (rank stores are contiguous per thread).
// ---------------------------------------------------------------------------
__global__ void k_deg(const int* __restrict__ dst, int E) {
    int t = blockIdx.x * blockDim.x + threadIdx.x;
    int e = t * 4;
    if (e + 3 < E) {
        int4 d = *reinterpret_cast<const int4*>(dst + e);
        int4 r;
        r.x = atomicAdd(&g_cnt[d.x], 1);
        r.y = atomicAdd(&g_cnt[d.y], 1);
        r.z = atomicAdd(&g_cnt[d.z], 1);
        r.w = atomicAdd(&g_cnt[d.w], 1);
        *reinterpret_cast<int4*>(g_rank + e) = r;
    } else {
        for (int k = e; k < E; k++) g_rank[k] = atomicAdd(&g_cnt[dst[k]], 1);
    }
}

// ---------------------------------------------------------------------------
// K3: fused allocation: block scan of counts + one atomic block-base claim.
//     Also computes dinv = rsqrt(1+cnt) and packs {dinv, x}.
// ---------------------------------------------------------------------------
__global__ void k_alloc(const int* __restrict__ x, int N) {
    __shared__ int swarp[TB / 32];
    __shared__ int sbb;
    int i    = blockIdx.x * TB + threadIdx.x;
    int lane = threadIdx.x & 31;
    int wid  = threadIdx.x >> 5;

    int c = (i < N) ? g_cnt[i] : 0;
    int incl = c;
#pragma unroll
    for (int o = 1; o < 32; o <<= 1) {
        int v = __shfl_up_sync(0xffffffffu, incl, o);
        if (lane >= o) incl += v;
    }
    if (lane == 31) swarp[wid] = incl;
    __syncthreads();
    if (threadIdx.x == 0) {
        int s = 0;
#pragma unroll
        for (int w = 0; w < TB / 32; w++) { int v = swarp[w]; swarp[w] = s; s += v; }
        sbb = atomicAdd(&g_total, s);
    }
    __syncthreads();
    if (i < N) {
        g_base[i] = sbb + swarp[wid] + (incl - c);   // exclusive segment start
        g_packed[i] = make_int2(__float_as_int(rsqrtf(1.0f + (float)c)), x[i]);
    }
}

// ---------------------------------------------------------------------------
// K4: ATOMIC-FREE scatter: pos = base[dst] + rank[e]; elist[pos] = packed[src].
//     8 edges/thread; all loads independent -> high MLP, ~3.25 wf/edge.
// ---------------------------------------------------------------------------
__global__ void k_build(const int* __restrict__ src, const int* __restrict__ dst,
                        int E) {
    int t = blockIdx.x * blockDim.x + threadIdx.x;
    int e = t * 8;
    if (e + 7 < E) {
        const int4* ps = reinterpret_cast<const int4*>(src + e);
        const int4* pd = reinterpret_cast<const int4*>(dst + e);
        const int4* pr = reinterpret_cast<const int4*>(g_rank + e);
        int4 s0 = ps[0], s1 = ps[1];
        int4 d0 = pd[0], d1 = pd[1];
        int4 r0 = pr[0], r1 = pr[1];
        int2 q0 = g_packed[s0.x];
        int2 q1 = g_packed[s0.y];
        int2 q2 = g_packed[s0.z];
        int2 q3 = g_packed[s0.w];
        int2 q4 = g_packed[s1.x];
        int2 q5 = g_packed[s1.y];
        int2 q6 = g_packed[s1.z];
        int2 q7 = g_packed[s1.w];
        int b0 = g_base[d0.x];
        int b1 = g_base[d0.y];
        int b2 = g_base[d0.z];
        int b3 = g_base[d0.w];
        int b4 = g_base[d1.x];
        int b5 = g_base[d1.y];
        int b6 = g_base[d1.z];
        int b7 = g_base[d1.w];
        g_elist[b0 + r0.x] = q0;
        g_elist[b1 + r0.y] = q1;
        g_elist[b2 + r0.z] = q2;
        g_elist[b3 + r0.w] = q3;
        g_elist[b4 + r1.x] = q4;
        g_elist[b5 + r1.y] = q5;
        g_elist[b6 + r1.z] = q6;
        g_elist[b7 + r1.w] = q7;
    } else {
        for (int k = e; k < E; k++) {
            g_elist[g_base[dst[k]] + g_rank[k]] = g_packed[src[k]];
        }
    }
}

// ---------------------------------------------------------------------------
// K5: 4 lanes per node, 8 EMB-columns per lane.
//     Edge loop reads CONTIGUOUS int2 payloads (no random gather).
// ---------------------------------------------------------------------------
__device__ __forceinline__ float tanha(float v) {
    float r;
    asm("tanh.approx.f32 %0, %1;" : "=f"(r) : "f"(v));
    return r;
}

#define WPITCH 33   // pad rows so random-row smem access spreads banks

__global__ void __launch_bounds__(TB)
k_aggpool(const int* __restrict__ batch,
          const float* __restrict__ W,
          const float* __restrict__ b_conv,
          const float* __restrict__ W_out,
          float* __restrict__ out, int N) {
    __shared__ float sW[IN_DIM * WPITCH];
    __shared__ float sb[EMB];
    __shared__ float so[EMB];
    for (int t = threadIdx.x; t < IN_DIM * EMB; t += blockDim.x) {
        int r = t / EMB, cc = t % EMB;
        sW[r * WPITCH + cc] = W[t];
    }
    if (threadIdx.x < EMB) {
        sb[threadIdx.x] = b_conv[threadIdx.x];
        so[threadIdx.x] = W_out[threadIdx.x];
    }
    __syncthreads();

    int t    = blockIdx.x * TB + threadIdx.x;
    int node = t >> 2;          // 4 lanes per node
    int sub  = t & 3;           // column group: columns [8*sub, 8*sub+8)
    if (node >= N) return;

    int2 p = g_packed[node];    // 4 lanes same address -> broadcast
    float dinv = __int_as_float(p.x);
    int   xi   = p.y;
    int   b0   = g_base[node];
    int   cnt  = g_cnt[node];
    int   col0 = sub * 8;

    float acc[8];
    {
        const float* row = &sW[xi * WPITCH + col0];
#pragma unroll
        for (int j = 0; j < 8; j++) acc[j] = dinv * row[j];
    }

    int k = 0;
    for (; k + 1 < cnt; k += 2) {          // 2-edge unroll for MLP
        int2 e0 = g_elist[b0 + k];
        int2 e1 = g_elist[b0 + k + 1];
        float d0 = __int_as_float(e0.x);
        float d1 = __int_as_float(e1.x);
        const float* r0 = &sW[e0.y * WPITCH + col0];
        const float* r1 = &sW[e1.y * WPITCH + col0];
#pragma unroll
        for (int j = 0; j < 8; j++) acc[j] += d0 * r0[j];
#pragma unroll
        for (int j = 0; j < 8; j++) acc[j] += d1 * r1[j];
    }
    if (k < cnt) {
        int2 e0 = g_elist[b0 + k];
        float d0 = __int_as_float(e0.x);
        const float* r0 = &sW[e0.y * WPITCH + col0];
#pragma unroll
        for (int j = 0; j < 8; j++) acc[j] += d0 * r0[j];
    }

    float res = 0.f;
#pragma unroll
    for (int j = 0; j < 8; j++)
        res += tanha(acc[j] * dinv + sb[col0 + j]) * so[col0 + j];

    // reduce across the 4 lanes of this node
    res += __shfl_xor_sync(0xffffffffu, res, 1);
    res += __shfl_xor_sync(0xffffffffu, res, 2);
    if (sub == 0) atomicAdd(&out[batch[node]], res);
}

// ---------------------------------------------------------------------------
// Launch
// Inputs: 0:x[N] i32, 1:edge_index[2E] i32, 2:batch[N] i32,
//         3:W[65*32] f32, 4:b_conv[32] f32, 5:W_out[32] f32, 6:b_out[1] f32
// Output: out[G] f32
// ---------------------------------------------------------------------------
extern "C" void kernel_launch(void* const* d_in, const int* in_sizes, int n_in,
                              void* d_out, int out_size) {
    const int*   x     = (const int*)d_in[0];
    const int*   eidx  = (const int*)d_in[1];
    const int*   batch = (const int*)d_in[2];
    const float* W     = (const float*)d_in[3];
    const float* bconv = (const float*)d_in[4];
    const float* Wout  = (const float*)d_in[5];
    const float* bout  = (const float*)d_in[6];
    float* out = (float*)d_out;

    int N = in_sizes[0];
    int E = in_sizes[1] / 2;
    int G = out_size;

    const int* src = eidx;
    const int* dst = eidx + E;

    int initN = N > G ? N : G;
    int nbE4  = ((E + 3) / 4 + TB - 1) / TB;
    int nbE8  = ((E + 7) / 8 + TB - 1) / TB;
    int nbN   = (N + TB - 1) / TB;
    int nbN4  = (int)(((size_t)N * 4 + TB - 1) / TB);

    k_init   <<<(initN + TB - 1) / TB, TB>>>(out, bout, N, G);
    k_deg    <<<nbE4, TB>>>(dst, E);
    k_alloc  <<<nbN, TB>>>(x, N);
    k_build  <<<nbE8, TB>>>(src, dst, E);
    k_aggpool<<<nbN4, TB>>>(batch, W, bconv, Wout, out, N);
}

// round 8
// speedup vs baseline: 1.1331x; 1.1331x over previous
#include <cuda_runtime.h>
#include <cstdint>

// Problem constants (fixed by the dataset)
#define NMAX    500000
#define EMAX    2000000
#define EMB     32
#define IN_DIM  65
#define TB      256
#define STRIDE  32            // ELL width; P(indegree > 32) ~ 1e-15 for this input
#define OVFCAP  8192

// Scratch (allocation-free rule: __device__ globals)
__device__ int g_novf;
__device__ __align__(128) int  g_cnt[NMAX];              // indegree (excl. self-loop)
__device__ __align__(128) int  g_ell[(size_t)NMAX * STRIDE]; // ELL: src ids, 64 MB
__device__ __align__(128) int2 g_ovf[OVFCAP];            // overflow {dst, src}
__device__ __align__(128) int2 g_packed[NMAX];           // {dinv bits, x}

// ---------------------------------------------------------------------------
// K1: zero counts + overflow, out[g] = b_out[0]
// ---------------------------------------------------------------------------
__global__ void k_init(float* __restrict__ out, const float* __restrict__ b_out,
                       int N, int G) {
    int i = blockIdx.x * blockDim.x + threadIdx.x;
    if (i < N) g_cnt[i] = 0;
    if (i < G) out[i] = b_out[0];
    if (i == 0) g_novf = 0;
}

// ---------------------------------------------------------------------------
// K2: ONE pass over edges: count indegree AND scatter src into ELL slot.
//     rank comes from the atomic return. Overflow (rank>=STRIDE) goes to a
//     tiny buffer handled by aggpool's heavy-node path (never on this input).
// ---------------------------------------------------------------------------
__device__ __forceinline__ void fill_one(int d, int s) {
    int r = atomicAdd(&g_cnt[d], 1);
    if (r < STRIDE) {
        g_ell[(size_t)d * STRIDE + r] = s;
    } else {
        int o = atomicAdd(&g_novf, 1);
        if (o < OVFCAP) g_ovf[o] = make_int2(d, s);
    }
}

__global__ void k_degfill(const int* __restrict__ src, const int* __restrict__ dst,
                          int E) {
    int t = blockIdx.x * blockDim.x + threadIdx.x;
    int e = t * 4;
    if (e + 3 < E) {
        int4 d4 = *reinterpret_cast<const int4*>(dst + e);
        int4 s4 = *reinterpret_cast<const int4*>(src + e);
        fill_one(d4.x, s4.x);
        fill_one(d4.y, s4.y);
        fill_one(d4.z, s4.z);
        fill_one(d4.w, s4.w);
    } else {
        for (int k = e; k < E; k++) fill_one(dst[k], src[k]);
    }
}

// ---------------------------------------------------------------------------
// K3: packed[i] = {rsqrt(1+cnt[i]), x[i]}
// ---------------------------------------------------------------------------
__global__ void k_pack(const int* __restrict__ x, int N) {
    int i = blockIdx.x * blockDim.x + threadIdx.x;
    if (i < N)
        g_packed[i] = make_int2(__float_as_int(rsqrtf(1.0f + (float)g_cnt[i])), x[i]);
}

// ---------------------------------------------------------------------------
// K4: 4 lanes per node, 8 EMB-columns per lane.
//     Per edge: contiguous ELL src read (broadcast) + random packed gather
//     (broadcast across the node's 4 lanes).
// ---------------------------------------------------------------------------
__device__ __forceinline__ float tanha(float v) {
    float r;
    asm("tanh.approx.f32 %0, %1;" : "=f"(r) : "f"(v));
    return r;
}

#define WPITCH 33   // pad rows so random-row smem access spreads banks

__global__ void __launch_bounds__(TB)
k_aggpool(const int* __restrict__ batch,
          const float* __restrict__ W,
          const float* __restrict__ b_conv,
          const float* __restrict__ W_out,
          float* __restrict__ out, int N) {
    __shared__ float sW[IN_DIM * WPITCH];
    __shared__ float sb[EMB];
    __shared__ float so[EMB];
    for (int t = threadIdx.x; t < IN_DIM * EMB; t += blockDim.x) {
        int r = t / EMB, cc = t % EMB;
        sW[r * WPITCH + cc] = W[t];
    }
    if (threadIdx.x < EMB) {
        sb[threadIdx.x] = b_conv[threadIdx.x];
        so[threadIdx.x] = W_out[threadIdx.x];
    }
    __syncthreads();

    int t    = blockIdx.x * TB + threadIdx.x;
    int node = t >> 2;          // 4 lanes per node
    int sub  = t & 3;           // column group: columns [8*sub, 8*sub+8)
    if (node >= N) return;

    int2 p = g_packed[node];    // broadcast across the 4 lanes
    float dinv = __int_as_float(p.x);
    int   xi   = p.y;
    int   cnt  = g_cnt[node];
    int   col0 = sub * 8;
    const int* row_ell = g_ell + (size_t)node * STRIDE;

    float acc[8];
    {
        const float* row = &sW[xi * WPITCH + col0];
#pragma unroll
        for (int j = 0; j < 8; j++) acc[j] = dinv * row[j];
    }

    int m = cnt <= STRIDE ? cnt : STRIDE;
    int k = 0;
    for (; k + 1 < m; k += 2) {            // 2-edge unroll for MLP
        int s0 = row_ell[k];
        int s1 = row_ell[k + 1];
        int2 p0 = g_packed[s0];
        int2 p1 = g_packed[s1];
        float d0 = __int_as_float(p0.x);
        float d1 = __int_as_float(p1.x);
        const float* r0 = &sW[p0.y * WPITCH + col0];
        const float* r1 = &sW[p1.y * WPITCH + col0];
#pragma unroll
        for (int j = 0; j < 8; j++) acc[j] += d0 * r0[j];
#pragma unroll
        for (int j = 0; j < 8; j++) acc[j] += d1 * r1[j];
    }
    if (k < m) {
        int s0 = row_ell[k];
        int2 p0 = g_packed[s0];
        float d0 = __int_as_float(p0.x);
        const float* r0 = &sW[p0.y * WPITCH + col0];
#pragma unroll
        for (int j = 0; j < 8; j++) acc[j] += d0 * r0[j];
    }

    // Heavy-node path: edges that overflowed the ELL width (never on this
    // input; loop trip count is 0). Kept for unconditional correctness.
    if (cnt > STRIDE) {
        int novf = g_novf;
        if (novf > OVFCAP) novf = OVFCAP;
        for (int j2 = 0; j2 < novf; j2++) {
            int2 ov = g_ovf[j2];
            if (ov.x == node) {
                int2 ps = g_packed[ov.y];
                float ds = __int_as_float(ps.x);
                const float* rr = &sW[ps.y * WPITCH + col0];
#pragma unroll
                for (int j = 0; j < 8; j++) acc[j] += ds * rr[j];
            }
        }
    }

    float res = 0.f;
#pragma unroll
    for (int j = 0; j < 8; j++)
        res += tanha(acc[j] * dinv + sb[col0 + j]) * so[col0 + j];

    // reduce across the 4 lanes of this node
    res += __shfl_xor_sync(0xffffffffu, res, 1);
    res += __shfl_xor_sync(0xffffffffu, res, 2);
    if (sub == 0) atomicAdd(&out[batch[node]], res);
}

// ---------------------------------------------------------------------------
// Launch
// Inputs: 0:x[N] i32, 1:edge_index[2E] i32, 2:batch[N] i32,
//         3:W[65*32] f32, 4:b_conv[32] f32, 5:W_out[32] f32, 6:b_out[1] f32
// Output: out[G] f32
// ---------------------------------------------------------------------------
extern "C" void kernel_launch(void* const* d_in, const int* in_sizes, int n_in,
                              void* d_out, int out_size) {
    const int*   x     = (const int*)d_in[0];
    const int*   eidx  = (const int*)d_in[1];
    const int*   batch = (const int*)d_in[2];
    const float* W     = (const float*)d_in[3];
    const float* bconv = (const float*)d_in[4];
    const float* Wout  = (const float*)d_in[5];
    const float* bout  = (const float*)d_in[6];
    float* out = (float*)d_out;

    int N = in_sizes[0];
    int E = in_sizes[1] / 2;
    int G = out_size;

    const int* src = eidx;
    const int* dst = eidx + E;

    int initN = N > G ? N : G;
    int nbE4  = ((E + 3) / 4 + TB - 1) / TB;
    int nbN   = (N + TB - 1) / TB;
    int nbN4  = (int)(((size_t)N * 4 + TB - 1) / TB);

    k_init   <<<(initN + TB - 1) / TB, TB>>>(out, bout, N, G);
    k_degfill<<<nbE4, TB>>>(src, dst, E);
    k_pack   <<<nbN, TB>>>(x, N);
    k_aggpool<<<nbN4, TB>>>(batch, W, bconv, Wout, out, N);
}